// round 14
// baseline (speedup 1.0000x reference)
#include <cuda_runtime.h>
#include <cuda_fp16.h>
#include <mma.h>
#include <cstdint>
#include <math.h>
#include <type_traits>

using namespace nvcuda;

// ---------------------------------------------------------------------------
// Problem constants
// ---------------------------------------------------------------------------
#define B       4
#define N_SEQ   2048
#define D_MODEL 1024
#define HEADS   16
#define DH      64
#define INNER   (HEADS*DH)  // 1024
#define ROT     32
#define SCALE   0.125f
#define LOG2E   1.4426950408889634f
#define QKV_LD  (3*INNER)   // 3072: fused Q|K|V row stride

// ---------------------------------------------------------------------------
// Scratch (static device globals — no allocation allowed)
// ---------------------------------------------------------------------------
__device__ __half g_qkv [(size_t)B*N_SEQ*QKV_LD];     // 48 MB  [8192][3072] Q|K|V
__device__ __half g_attn[(size_t)B*N_SEQ*INNER];      // 16 MB
__device__ __half g_qh  [(size_t)B*N_SEQ*D_MODEL];    // 16 MB queries in half
__device__ __half g_wqkv[(size_t)D_MODEL*QKV_LD];     // 6 MB  [1024][3072] Wq|Wkv
__device__ __half g_wo  [(size_t)INNER*D_MODEL];      // 2 MB

__device__ __forceinline__ uint32_t f2h2(float a, float b) {
    __half2 h = __floats2half2_rn(a, b);
    return *(uint32_t*)&h;
}
__device__ __forceinline__ uint32_t h2ex2(uint32_t x) {   // 2^x on f16x2
    uint32_t r;
    asm("ex2.approx.f16x2 %0, %1;" : "=r"(r) : "r"(x));
    return r;
}
__device__ __forceinline__ float2 h2f2(uint32_t h2) {
    __half2 v = *(__half2*)&h2;
    return __half22float2(v);
}
__device__ __forceinline__ uint32_t smem_u32(const void* p) {
    uint32_t a;
    asm("{ .reg .u64 t; cvta.to.shared.u64 t, %1; cvt.u32.u64 %0, t; }"
        : "=r"(a) : "l"(p));
    return a;
}
__device__ __forceinline__ void ldsm_x4(uint32_t& r0, uint32_t& r1,
                                        uint32_t& r2, uint32_t& r3, uint32_t a) {
    asm volatile("ldmatrix.sync.aligned.m8n8.x4.shared.b16 {%0,%1,%2,%3}, [%4];"
                 : "=r"(r0), "=r"(r1), "=r"(r2), "=r"(r3) : "r"(a));
}
__device__ __forceinline__ void ldsm_x4_t(uint32_t& r0, uint32_t& r1,
                                          uint32_t& r2, uint32_t& r3, uint32_t a) {
    asm volatile("ldmatrix.sync.aligned.m8n8.x4.trans.shared.b16 {%0,%1,%2,%3}, [%4];"
                 : "=r"(r0), "=r"(r1), "=r"(r2), "=r"(r3) : "r"(a));
}
__device__ __forceinline__ void mma16816(float* c, const uint32_t* a,
                                         uint32_t b0, uint32_t b1) {
    asm volatile(
        "mma.sync.aligned.m16n8k16.row.col.f32.f16.f16.f32 "
        "{%0,%1,%2,%3}, {%4,%5,%6,%7}, {%8,%9}, {%0,%1,%2,%3};"
        : "+f"(c[0]), "+f"(c[1]), "+f"(c[2]), "+f"(c[3])
        : "r"(a[0]), "r"(a[1]), "r"(a[2]), "r"(a[3]), "r"(b0), "r"(b1));
}
__device__ __forceinline__ void cp16(uint32_t dst, const void* src) {
    asm volatile("cp.async.cg.shared.global [%0], [%1], 16;"
                 :: "r"(dst), "l"(src) : "memory");
}
__device__ __forceinline__ void cp_commit() {
    asm volatile("cp.async.commit_group;" ::: "memory");
}
template<int N>
__device__ __forceinline__ void cp_wait() {
    asm volatile("cp.async.wait_group %0;" :: "n"(N) : "memory");
}

// ---------------------------------------------------------------------------
// fp32 -> fp16 bulk convert; contiguous dst
// ---------------------------------------------------------------------------
__global__ void f2h_kernel(const float* __restrict__ src, __half* __restrict__ dst,
                           int n8)
{
    const int i = blockIdx.x * blockDim.x + threadIdx.x;
    if (i >= n8) return;
    const float4 a = ((const float4*)src)[2*i];
    const float4 b = ((const float4*)src)[2*i + 1];
    uint4 h;
    h.x = f2h2(a.x, a.y);
    h.y = f2h2(a.z, a.w);
    h.z = f2h2(b.x, b.y);
    h.w = f2h2(b.z, b.w);
    ((uint4*)dst)[i] = h;
}

// fp32 [rows, srcN] -> fp16 into dst with row stride dstLD (column-block concat)
__global__ void f2h_cols_kernel(const float* __restrict__ src, __half* __restrict__ dst,
                                int srcN, int dstLD, int n8)
{
    const int i = blockIdx.x * blockDim.x + threadIdx.x;
    if (i >= n8) return;
    const int gpr = srcN >> 3;           // 8-elem groups per row
    const int r = i / gpr, c8 = i - r*gpr;
    const float4 a = *(const float4*)(src + (size_t)r*srcN + c8*8);
    const float4 b = *(const float4*)(src + (size_t)r*srcN + c8*8 + 4);
    uint4 h;
    h.x = f2h2(a.x, a.y);
    h.y = f2h2(a.z, a.w);
    h.z = f2h2(b.x, b.y);
    h.w = f2h2(b.z, b.w);
    *(uint4*)(dst + (size_t)r*dstLD + c8*8) = h;
}

// ---------------------------------------------------------------------------
// fp16 wmma GEMM: C = A @ B (+bias via accumulator init); A,B half in gmem.
// Tile 128x128x32, 256 threads, 2 CTAs/SM, register double-buffer.
// ---------------------------------------------------------------------------
#define GBM 128
#define GBN 128
#define GBK 32
#define A_LDH 40
#define B_LDH 136
#define STAGE_H (GBM*A_LDH + GBK*B_LDH)            // 9472 halfs
#define GEMM_BIAS_OFF (2*STAGE_H)
#define GEMM_SMEM (2*STAGE_H*2 + 16*GBN*4)         // 46080 B

template<typename TC>
__global__ __launch_bounds__(256, 2)
void gemm_f16_kernel(const __half* __restrict__ A, const __half* __restrict__ Bm,
                     const float* __restrict__ bias, TC* __restrict__ C,
                     int M, int N, int K)
{
    extern __shared__ __half smh[];
    const int tid = threadIdx.x;
    const int wid = tid >> 5;
    const int bx = blockIdx.x;
    const int by = blockIdx.y;
    const int wm = (wid & 1) * 64;
    const int wn = (wid >> 1) * 32;

    float* biasRep = (float*)(smh + GEMM_BIAS_OFF);   // [16][GBN]
    if (bias) {
        const float bval = __ldg(bias + bx*GBN + (tid & 127));
        biasRep[(tid >> 7) * GBN + (tid & 127)] = bval;
        #pragma unroll
        for (int rr = 2; rr < 16; rr += 2)
            biasRep[(rr + (tid >> 7)) * GBN + (tid & 127)] = bval;
    }

    wmma::fragment<wmma::accumulator, 16, 16, 16, float> acc[4][2];

    const __half* Ag = A + (size_t)(by*GBM) * K;
    const __half* Bg = Bm + (size_t)bx * GBN;

    uint4 a_st[2], b_st[2];

    auto load_chunk = [&](int k0) {
        #pragma unroll
        for (int s = 0; s < 2; s++) {
            const int f = tid + s*256;           // uint4 idx over 128x32 halfs
            const int r = f >> 2, g = f & 3;
            a_st[s] = *(const uint4*)(Ag + (size_t)r*K + k0 + g*8);
        }
        #pragma unroll
        for (int s = 0; s < 2; s++) {
            const int f = tid + s*256;           // uint4 idx over 32x128 halfs
            const int r = f >> 4, g = f & 15;
            b_st[s] = *(const uint4*)(Bg + (size_t)(k0 + r)*N + g*8);
        }
    };
    auto store_chunk = [&](int p) {
        __half* As = smh + p*STAGE_H;
        __half* Bs = As + GBM*A_LDH;
        #pragma unroll
        for (int s = 0; s < 2; s++) {
            const int f = tid + s*256;
            const int r = f >> 2, g = f & 3;
            *(uint4*)(As + r*A_LDH + g*8) = a_st[s];
        }
        #pragma unroll
        for (int s = 0; s < 2; s++) {
            const int f = tid + s*256;
            const int r = f >> 4, g = f & 15;
            *(uint4*)(Bs + r*B_LDH + g*8) = b_st[s];
        }
    };
    auto compute = [&](int p) {
        const __half* As = smh + p*STAGE_H;
        const __half* Bs = As + GBM*A_LDH;
        #pragma unroll
        for (int ks = 0; ks < 2; ks++) {
            wmma::fragment<wmma::matrix_a, 16, 16, 16, __half, wmma::row_major> af[4];
            wmma::fragment<wmma::matrix_b, 16, 16, 16, __half, wmma::row_major> bf[2];
            #pragma unroll
            for (int mi = 0; mi < 4; mi++)
                wmma::load_matrix_sync(af[mi], As + (wm + mi*16)*A_LDH + ks*16, A_LDH);
            #pragma unroll
            for (int ni = 0; ni < 2; ni++)
                wmma::load_matrix_sync(bf[ni], Bs + (ks*16)*B_LDH + wn + ni*16, B_LDH);
            #pragma unroll
            for (int mi = 0; mi < 4; mi++)
                #pragma unroll
                for (int ni = 0; ni < 2; ni++)
                    wmma::mma_sync(acc[mi][ni], af[mi], bf[ni], acc[mi][ni]);
        }
    };

    const int NC = K / GBK;
    load_chunk(0);
    store_chunk(0);
    __syncthreads();

    if (bias) {
        #pragma unroll
        for (int mi = 0; mi < 4; mi++)
            #pragma unroll
            for (int ni = 0; ni < 2; ni++)
                wmma::load_matrix_sync(acc[mi][ni], biasRep + wn + ni*16, GBN,
                                       wmma::mem_row_major);
    } else {
        #pragma unroll
        for (int mi = 0; mi < 4; mi++)
            #pragma unroll
            for (int ni = 0; ni < 2; ni++)
                wmma::fill_fragment(acc[mi][ni], 0.f);
    }

    for (int c = 0; c < NC; c++) {
        const int p = c & 1;
        if (c + 1 < NC) load_chunk((c + 1) * GBK);
        compute(p);
        if (c + 1 < NC) store_chunk(p ^ 1);
        __syncthreads();
    }

    if constexpr (std::is_same<TC, __half>::value) {
        #pragma unroll
        for (int mi = 0; mi < 4; mi++)
            #pragma unroll
            for (int ni = 0; ni < 2; ni++) {
                wmma::fragment<wmma::accumulator, 16, 16, 16, __half> h;
                #pragma unroll
                for (int t = 0; t < h.num_elements; t++)
                    h.x[t] = __float2half(acc[mi][ni].x[t]);
                wmma::store_matrix_sync(
                    C + (size_t)(by*GBM + wm + mi*16)*N + bx*GBN + wn + ni*16,
                    h, N, wmma::mem_row_major);
            }
    } else {
        #pragma unroll
        for (int mi = 0; mi < 4; mi++)
            #pragma unroll
            for (int ni = 0; ni < 2; ni++)
                wmma::store_matrix_sync(
                    C + (size_t)(by*GBM + wm + mi*16)*N + bx*GBN + wn + ni*16,
                    acc[mi][ni], N, wmma::mem_row_major);
    }
}

// ---------------------------------------------------------------------------
// RoPE on fused QKV buffer (which=0 -> Q cols, which=1 -> K cols)
// ---------------------------------------------------------------------------
__global__ void rope_kernel(__half* __restrict__ qkv)
{
    const int total = B * N_SEQ * HEADS * (ROT/2);
    int idx = blockIdx.x * blockDim.x + threadIdx.x;
    if (idx >= 2*total) return;
    const int which = (idx >= total);
    int t = idx - which*total;
    const int i   = t & 15;  t >>= 4;
    const int h   = t & 15;  t >>= 4;
    const int pos = t & (N_SEQ-1); t >>= 11;
    const int b   = t;

    const float inv_freq = powf(10000.f, -(float)(2*i) / (float)ROT);
    const float ang = (float)pos * inv_freq;
    float s, c;
    sincosf(ang, &s, &c);

    __half* base = qkv + ((size_t)(b*N_SEQ + pos)) * QKV_LD
                       + which*INNER + h*DH;
    const float x1 = __half2float(base[2*i]);
    const float x2 = __half2float(base[2*i+1]);
    base[2*i]   = __float2half(x1*c - x2*s);
    base[2*i+1] = __float2half(x2*c + x1*s);
}

// ---------------------------------------------------------------------------
// Flash attention (R12 structure): raw mma.sync, 32 q-rows/warp, 2-stage
// cp.async K/V; P = 2^S via ex2.approx.f16x2 (l summed from the SAME rounded
// f16 values -> numerator/denominator consistent, matches R8 numerics).
// Reads fused QKV buffer: Q at col 0, K at col 1024, V at col 2048.
// ---------------------------------------------------------------------------
#define AQ   256
#define AK   64
#define ALD  72
#define OFF_QS 0
#define KV_SZ (AK*ALD)                  // 4608
#define OFF_K0 (AQ*ALD)                 // 18432
#define OFF_K1 (OFF_K0 + KV_SZ)
#define OFF_V0 (OFF_K1 + KV_SZ)
#define OFF_V1 (OFF_V0 + KV_SZ)
#define ATTN_H (OFF_V1 + KV_SZ)         // 36864 halfs
#define ATTN_SMEM (ATTN_H*2)            // 73728 B

__global__ __launch_bounds__(256, 2)
void attn_kernel(const __half* __restrict__ qkv, __half* __restrict__ out)
{
    extern __shared__ __half smh[];
    const uint32_t smbase = smem_u32(smh);

    const int bh = blockIdx.x;
    const int b  = bh >> 4;
    const int h  = bh & 15;
    const int qt = blockIdx.y;
    const int tid  = threadIdx.x;
    const int w    = tid >> 5;
    const int lane = tid & 31;
    const int gid  = lane >> 2;
    const int tig  = lane & 3;
    const int mi   = lane >> 3;

    // ---- load Q tile (256x64) from QKV, scaled by SCALE*log2e
    const __half* qbase = qkv + ((size_t)(b*N_SEQ) + qt*AQ) * QKV_LD + h*DH;
    const __half2 sc2 = __floats2half2_rn(SCALE*LOG2E, SCALE*LOG2E);
    #pragma unroll
    for (int s = 0; s < 8; s++) {
        const int f = tid + s*256;
        const int r = f >> 3, g = f & 7;
        uint4 v = *(const uint4*)(qbase + (size_t)r*QKV_LD + g*8);
        __half2* hp = (__half2*)&v;
        #pragma unroll
        for (int j = 0; j < 4; j++) hp[j] = __hmul2(hp[j], sc2);
        *(uint4*)(smh + OFF_QS + r*ALD + g*8) = v;
    }

    const __half* kv_bh = qkv + ((size_t)(b*N_SEQ)) * QKV_LD + INNER + h*DH;
    auto issue_tile = [&](int kt) {
        const int p = kt & 1;
        const __half* kbase = kv_bh + (size_t)(kt*AK) * QKV_LD;
        const uint32_t Kb = smbase + (uint32_t)((p ? OFF_K1 : OFF_K0) * 2);
        const uint32_t Vb = smbase + (uint32_t)((p ? OFF_V1 : OFF_V0) * 2);
        #pragma unroll
        for (int s = 0; s < 2; s++) {
            const int f = tid + s*256;
            const int r = f >> 3, g = f & 7;
            const uint32_t off = (uint32_t)((r*ALD + g*8) * 2);
            cp16(Kb + off, kbase + (size_t)r*QKV_LD + g*8);
            cp16(Vb + off, kbase + INNER + (size_t)r*QKV_LD + g*8);
        }
        cp_commit();
    };

    issue_tile(0);
    __syncthreads();

    uint32_t qa[2][4][4];
    #pragma unroll
    for (int m = 0; m < 2; m++) {
        const int qrow = w*32 + m*16 + (mi & 1)*8 + (lane & 7);
        #pragma unroll
        for (int kk = 0; kk < 4; kk++) {
            const uint32_t a = smbase +
                (uint32_t)((OFF_QS + qrow*ALD + kk*16 + (mi >> 1)*8) * 2);
            ldsm_x4(qa[m][kk][0], qa[m][kk][1], qa[m][kk][2], qa[m][kk][3], a);
        }
    }

    float o[2][8][4];
    #pragma unroll
    for (int m = 0; m < 2; m++)
        #pragma unroll
        for (int nt = 0; nt < 8; nt++)
            #pragma unroll
            for (int e = 0; e < 4; e++) o[m][nt][e] = 0.f;
    float lsum[2][2];
    lsum[0][0] = lsum[0][1] = lsum[1][0] = lsum[1][1] = 0.f;

    const int krow_base = ((mi >> 1) << 3) + (lane & 7);
    const int kcol_off  = (mi & 1) * 8;
    const int vrow_base = ((mi & 1) << 3) + (lane & 7);
    const int vcol_off  = (mi >> 1) * 8;

    const int NT = N_SEQ/AK;   // 32
    for (int kt = 0; kt < NT; kt++) {
        const int p = kt & 1;
        cp_wait<0>();
        __syncthreads();
        if (kt + 1 < NT) issue_tile(kt + 1);

        const uint32_t Kb = smbase + (uint32_t)((p ? OFF_K1 : OFF_K0) * 2);
        const uint32_t Vb = smbase + (uint32_t)((p ? OFF_V1 : OFF_V0) * 2);

        #pragma unroll
        for (int jc = 0; jc < 4; jc++) {
            float sa0[4] = {0.f,0.f,0.f,0.f};
            float sa1[4] = {0.f,0.f,0.f,0.f};
            float sb0[4] = {0.f,0.f,0.f,0.f};
            float sb1[4] = {0.f,0.f,0.f,0.f};
            const int krow = jc*16 + krow_base;
            #pragma unroll
            for (int kk = 0; kk < 4; kk++) {
                uint32_t b0, b1, b2, b3;
                ldsm_x4(b0, b1, b2, b3,
                        Kb + (uint32_t)((krow*ALD + kk*16 + kcol_off) * 2));
                mma16816(sa0, qa[0][kk], b0, b1);
                mma16816(sa1, qa[0][kk], b2, b3);
                mma16816(sb0, qa[1][kk], b0, b1);
                mma16816(sb1, qa[1][kk], b2, b3);
            }
            // ---- P = 2^S via f16x2 MUFU; l from the SAME rounded values
            uint32_t pa[2][4];
            pa[0][0] = h2ex2(f2h2(sa0[0], sa0[1]));
            pa[0][1] = h2ex2(f2h2(sa0[2], sa0[3]));
            pa[0][2] = h2ex2(f2h2(sa1[0], sa1[1]));
            pa[0][3] = h2ex2(f2h2(sa1[2], sa1[3]));
            pa[1][0] = h2ex2(f2h2(sb0[0], sb0[1]));
            pa[1][1] = h2ex2(f2h2(sb0[2], sb0[3]));
            pa[1][2] = h2ex2(f2h2(sb1[0], sb1[1]));
            pa[1][3] = h2ex2(f2h2(sb1[2], sb1[3]));
            #pragma unroll
            for (int m = 0; m < 2; m++) {
                const float2 eA = h2f2(pa[m][0]);
                const float2 eB = h2f2(pa[m][2]);
                lsum[m][0] += (eA.x + eA.y) + (eB.x + eB.y);
                const float2 eC = h2f2(pa[m][1]);
                const float2 eD = h2f2(pa[m][3]);
                lsum[m][1] += (eC.x + eC.y) + (eD.x + eD.y);
            }
            const int vrow = jc*16 + vrow_base;
            #pragma unroll
            for (int vp = 0; vp < 4; vp++) {
                uint32_t v0, v1, v2, v3;
                ldsm_x4_t(v0, v1, v2, v3,
                          Vb + (uint32_t)((vrow*ALD + vp*16 + vcol_off) * 2));
                mma16816(o[0][2*vp],   pa[0], v0, v1);
                mma16816(o[0][2*vp+1], pa[0], v2, v3);
                mma16816(o[1][2*vp],   pa[1], v0, v1);
                mma16816(o[1][2*vp+1], pa[1], v2, v3);
            }
        }
    }

    #pragma unroll
    for (int m = 0; m < 2; m++) {
        float l0 = lsum[m][0], l1 = lsum[m][1];
        l0 += __shfl_xor_sync(0xFFFFFFFFu, l0, 1);
        l0 += __shfl_xor_sync(0xFFFFFFFFu, l0, 2);
        l1 += __shfl_xor_sync(0xFFFFFFFFu, l1, 1);
        l1 += __shfl_xor_sync(0xFFFFFFFFu, l1, 2);
        const float inv0 = 1.f / l0;
        const float inv1 = 1.f / l1;

        const int r0 = qt*AQ + w*32 + m*16 + gid;
        __half* ob0 = out + ((size_t)(b*N_SEQ) + r0) * INNER + h*DH + tig*2;
        __half* ob1 = ob0 + (size_t)8 * INNER;
        #pragma unroll
        for (int nt = 0; nt < 8; nt++) {
            *(uint32_t*)(ob0 + nt*8) = f2h2(o[m][nt][0]*inv0, o[m][nt][1]*inv0);
            *(uint32_t*)(ob1 + nt*8) = f2h2(o[m][nt][2]*inv1, o[m][nt][3]*inv1);
        }
    }
}

// ---------------------------------------------------------------------------
// launch
// ---------------------------------------------------------------------------
extern "C" void kernel_launch(void* const* d_in, const int* in_sizes, int n_in,
                              void* d_out, int out_size)
{
    const float* queries = (const float*)d_in[0];
    const float* Wq      = (const float*)d_in[1];
    const float* Wkv     = (const float*)d_in[2];
    const float* Wout    = (const float*)d_in[3];
    const float* bout    = (const float*)d_in[4];
    float* out = (float*)d_out;

    __half *qkv, *attnp, *qh, *wqkv, *wo;
    cudaGetSymbolAddress((void**)&qkv,   g_qkv);
    cudaGetSymbolAddress((void**)&attnp, g_attn);
    cudaGetSymbolAddress((void**)&qh,    g_qh);
    cudaGetSymbolAddress((void**)&wqkv,  g_wqkv);
    cudaGetSymbolAddress((void**)&wo,    g_wo);

    static bool attr_set = false;
    if (!attr_set) {
        cudaFuncSetAttribute(attn_kernel,
                             cudaFuncAttributeMaxDynamicSharedMemorySize,
                             (int)ATTN_SMEM);
        cudaFuncSetAttribute(gemm_f16_kernel<__half>,
                             cudaFuncAttributeMaxDynamicSharedMemorySize,
                             GEMM_SMEM);
        cudaFuncSetAttribute(gemm_f16_kernel<float>,
                             cudaFuncAttributeMaxDynamicSharedMemorySize,
                             GEMM_SMEM);
        attr_set = true;
    }

    const int M = B * N_SEQ;  // 8192

    // ---- one-shot fp32 -> fp16 conversions (weights concatenated: Wq|Wkv)
    {
        const int nq8 = (M * D_MODEL) / 8;
        f2h_kernel<<<(nq8 + 255)/256, 256>>>(queries, qh, nq8);
        const int nwq8 = (D_MODEL * INNER) / 8;
        f2h_cols_kernel<<<(nwq8 + 255)/256, 256>>>(Wq, wqkv, INNER, QKV_LD, nwq8);
        const int nwkv8 = (D_MODEL * 2*INNER) / 8;
        f2h_cols_kernel<<<(nwkv8 + 255)/256, 256>>>(Wkv, wqkv + INNER,
                                                    2*INNER, QKV_LD, nwkv8);
        const int nwo8 = (INNER * D_MODEL) / 8;
        f2h_kernel<<<(nwo8 + 255)/256, 256>>>(Wout, wo, nwo8);
    }

    // QKV = queries @ [Wq|Wkv]  -> half [8192, 3072]
    {
        dim3 grid(QKV_LD/GBN, M/GBM);   // 24 x 64 = 1536 CTAs
        gemm_f16_kernel<__half><<<grid, 256, GEMM_SMEM>>>(
            qh, wqkv, nullptr, qkv, M, QKV_LD, D_MODEL);
    }
    // RoPE (in-place on Q and K column blocks)
    {
        const int total = 2 * B * N_SEQ * HEADS * (ROT/2);
        rope_kernel<<<(total + 255)/256, 256>>>(qkv);
    }
    // attention -> half
    {
        dim3 grid(B*HEADS, N_SEQ/AQ);
        attn_kernel<<<grid, 256, ATTN_SMEM>>>(qkv, attnp);
    }
    // out = attn @ Wout + bout -> float
    {
        dim3 grid(D_MODEL/GBN, M/GBM);
        gemm_f16_kernel<float><<<grid, 256, GEMM_SMEM>>>(
            attnp, wo, bout, out, M, D_MODEL, INNER);
    }
}

// round 15
// speedup vs baseline: 1.0583x; 1.0583x over previous
#include <cuda_runtime.h>
#include <cuda_fp16.h>
#include <mma.h>
#include <cstdint>
#include <math.h>
#include <type_traits>

using namespace nvcuda;

// ---------------------------------------------------------------------------
// Problem constants
// ---------------------------------------------------------------------------
#define B       4
#define N_SEQ   2048
#define D_MODEL 1024
#define HEADS   16
#define DH      64
#define INNER   (HEADS*DH)  // 1024
#define ROT     32
#define SCALE   0.125f
#define LOG2E   1.4426950408889634f
#define QKV_LD  (3*INNER)   // 3072: fused Q|K|V row stride

// ---------------------------------------------------------------------------
// Scratch (static device globals — no allocation allowed)
// ---------------------------------------------------------------------------
__device__ __half g_qkv [(size_t)B*N_SEQ*QKV_LD];     // 48 MB  [8192][3072] Q|K|V
__device__ __half g_attn[(size_t)B*N_SEQ*INNER];      // 16 MB
__device__ __half g_qh  [(size_t)B*N_SEQ*D_MODEL];    // 16 MB queries in half
__device__ __half g_wqkv[(size_t)D_MODEL*QKV_LD];     // 6 MB  [1024][3072] Wq|Wkv
__device__ __half g_wo  [(size_t)INNER*D_MODEL];      // 2 MB

__device__ __forceinline__ uint32_t f2h2(float a, float b) {
    __half2 h = __floats2half2_rn(a, b);
    return *(uint32_t*)&h;
}
__device__ __forceinline__ float ex2f(float x) {
    float r;
    asm("ex2.approx.f32 %0, %1;" : "=f"(r) : "f"(x));
    return r;
}
__device__ __forceinline__ uint32_t smem_u32(const void* p) {
    uint32_t a;
    asm("{ .reg .u64 t; cvta.to.shared.u64 t, %1; cvt.u32.u64 %0, t; }"
        : "=r"(a) : "l"(p));
    return a;
}
__device__ __forceinline__ void ldsm_x4(uint32_t& r0, uint32_t& r1,
                                        uint32_t& r2, uint32_t& r3, uint32_t a) {
    asm volatile("ldmatrix.sync.aligned.m8n8.x4.shared.b16 {%0,%1,%2,%3}, [%4];"
                 : "=r"(r0), "=r"(r1), "=r"(r2), "=r"(r3) : "r"(a));
}
__device__ __forceinline__ void ldsm_x4_t(uint32_t& r0, uint32_t& r1,
                                          uint32_t& r2, uint32_t& r3, uint32_t a) {
    asm volatile("ldmatrix.sync.aligned.m8n8.x4.trans.shared.b16 {%0,%1,%2,%3}, [%4];"
                 : "=r"(r0), "=r"(r1), "=r"(r2), "=r"(r3) : "r"(a));
}
__device__ __forceinline__ void mma16816(float* c, const uint32_t* a,
                                         uint32_t b0, uint32_t b1) {
    asm volatile(
        "mma.sync.aligned.m16n8k16.row.col.f32.f16.f16.f32 "
        "{%0,%1,%2,%3}, {%4,%5,%6,%7}, {%8,%9}, {%0,%1,%2,%3};"
        : "+f"(c[0]), "+f"(c[1]), "+f"(c[2]), "+f"(c[3])
        : "r"(a[0]), "r"(a[1]), "r"(a[2]), "r"(a[3]), "r"(b0), "r"(b1));
}
__device__ __forceinline__ void cp16(uint32_t dst, const void* src) {
    asm volatile("cp.async.cg.shared.global [%0], [%1], 16;"
                 :: "r"(dst), "l"(src) : "memory");
}
__device__ __forceinline__ void cp_commit() {
    asm volatile("cp.async.commit_group;" ::: "memory");
}
template<int N>
__device__ __forceinline__ void cp_wait() {
    asm volatile("cp.async.wait_group %0;" :: "n"(N) : "memory");
}

// ---------------------------------------------------------------------------
// fp32 -> fp16 bulk convert; contiguous dst
// ---------------------------------------------------------------------------
__global__ void f2h_kernel(const float* __restrict__ src, __half* __restrict__ dst,
                           int n8)
{
    const int i = blockIdx.x * blockDim.x + threadIdx.x;
    if (i >= n8) return;
    const float4 a = ((const float4*)src)[2*i];
    const float4 b = ((const float4*)src)[2*i + 1];
    uint4 h;
    h.x = f2h2(a.x, a.y);
    h.y = f2h2(a.z, a.w);
    h.z = f2h2(b.x, b.y);
    h.w = f2h2(b.z, b.w);
    ((uint4*)dst)[i] = h;
}

// fp32 [rows, srcN] -> fp16 into dst with row stride dstLD (column-block concat)
__global__ void f2h_cols_kernel(const float* __restrict__ src, __half* __restrict__ dst,
                                int srcN, int dstLD, int n8)
{
    const int i = blockIdx.x * blockDim.x + threadIdx.x;
    if (i >= n8) return;
    const int gpr = srcN >> 3;           // 8-elem groups per row
    const int r = i / gpr, c8 = i - r*gpr;
    const float4 a = *(const float4*)(src + (size_t)r*srcN + c8*8);
    const float4 b = *(const float4*)(src + (size_t)r*srcN + c8*8 + 4);
    uint4 h;
    h.x = f2h2(a.x, a.y);
    h.y = f2h2(a.z, a.w);
    h.z = f2h2(b.x, b.y);
    h.w = f2h2(b.z, b.w);
    *(uint4*)(dst + (size_t)r*dstLD + c8*8) = h;
}

// ---------------------------------------------------------------------------
// fp16 wmma GEMM: C = A @ B (+bias via accumulator init); A,B half in gmem.
// Tile 128x128x64, 256 threads, 2 CTAs/SM, 2-stage cp.async pipeline
// (wait<0> -> barrier -> issue next -> compute; no register staging, no STS).
// ---------------------------------------------------------------------------
#define GBM 128
#define GBN 128
#define GBK 64
#define A_LDH 72      // 64 + 8 pad
#define B_LDH 136     // 128 + 8 pad
#define STAGE_H (GBM*A_LDH + GBK*B_LDH)            // 9216+8704 = 17920 halfs
#define GEMM_BIAS_OFF (2*STAGE_H)
#define GEMM_SMEM (2*STAGE_H*2 + 16*GBN*4)         // 71680 + 8192 = 79872 B

template<typename TC>
__global__ __launch_bounds__(256, 2)
void gemm_f16_kernel(const __half* __restrict__ A, const __half* __restrict__ Bm,
                     const float* __restrict__ bias, TC* __restrict__ C,
                     int M, int N, int K)
{
    extern __shared__ __half smh[];
    const uint32_t smbase = smem_u32(smh);
    const int tid = threadIdx.x;
    const int wid = tid >> 5;
    const int bx = blockIdx.x;
    const int by = blockIdx.y;
    const int wm = (wid & 1) * 64;
    const int wn = (wid >> 1) * 32;

    float* biasRep = (float*)(smh + GEMM_BIAS_OFF);   // [16][GBN]
    if (bias) {
        const float bval = __ldg(bias + bx*GBN + (tid & 127));
        biasRep[(tid >> 7) * GBN + (tid & 127)] = bval;
        #pragma unroll
        for (int rr = 2; rr < 16; rr += 2)
            biasRep[(rr + (tid >> 7)) * GBN + (tid & 127)] = bval;
    }

    wmma::fragment<wmma::accumulator, 16, 16, 16, float> acc[4][2];

    const __half* Ag = A + (size_t)(by*GBM) * K;
    const __half* Bg = Bm + (size_t)bx * GBN;

    // issue one K-chunk (A 128x64, B 64x128) into stage c&1 via cp.async
    auto issue_chunk = [&](int c) {
        const int p = c & 1;
        const int k0 = c * GBK;
        const uint32_t As = smbase + (uint32_t)(p*STAGE_H)*2;
        const uint32_t Bs = As + (uint32_t)(GBM*A_LDH)*2;
        #pragma unroll
        for (int s = 0; s < 4; s++) {
            const int f = tid + s*256;           // 1024 x 16B over A tile
            const int r = f >> 3, g = f & 7;
            cp16(As + (uint32_t)((r*A_LDH + g*8)*2),
                 Ag + (size_t)r*K + k0 + g*8);
        }
        #pragma unroll
        for (int s = 0; s < 4; s++) {
            const int f = tid + s*256;           // 1024 x 16B over B tile
            const int r = f >> 4, g = f & 15;
            cp16(Bs + (uint32_t)((r*B_LDH + g*8)*2),
                 Bg + (size_t)(k0 + r)*N + g*8);
        }
        cp_commit();
    };
    auto compute = [&](int p) {
        const __half* As = smh + p*STAGE_H;
        const __half* Bs = As + GBM*A_LDH;
        #pragma unroll
        for (int ks = 0; ks < 4; ks++) {
            wmma::fragment<wmma::matrix_a, 16, 16, 16, __half, wmma::row_major> af[4];
            wmma::fragment<wmma::matrix_b, 16, 16, 16, __half, wmma::row_major> bf[2];
            #pragma unroll
            for (int mi = 0; mi < 4; mi++)
                wmma::load_matrix_sync(af[mi], As + (wm + mi*16)*A_LDH + ks*16, A_LDH);
            #pragma unroll
            for (int ni = 0; ni < 2; ni++)
                wmma::load_matrix_sync(bf[ni], Bs + (ks*16)*B_LDH + wn + ni*16, B_LDH);
            #pragma unroll
            for (int mi = 0; mi < 4; mi++)
                #pragma unroll
                for (int ni = 0; ni < 2; ni++)
                    wmma::mma_sync(acc[mi][ni], af[mi], bf[ni], acc[mi][ni]);
        }
    };

    const int NC = K / GBK;   // 16
    issue_chunk(0);
    cp_wait<0>();
    __syncthreads();          // chunk0 + biasRep visible

    if (bias) {
        #pragma unroll
        for (int mi = 0; mi < 4; mi++)
            #pragma unroll
            for (int ni = 0; ni < 2; ni++)
                wmma::load_matrix_sync(acc[mi][ni], biasRep + wn + ni*16, GBN,
                                       wmma::mem_row_major);
    } else {
        #pragma unroll
        for (int mi = 0; mi < 4; mi++)
            #pragma unroll
            for (int ni = 0; ni < 2; ni++)
                wmma::fill_fragment(acc[mi][ni], 0.f);
    }

    for (int c = 0; c < NC; c++) {
        if (c > 0) {
            cp_wait<0>();      // chunk c arrived
            __syncthreads();   // all warps retired chunk c-1 -> stage free
        }
        if (c + 1 < NC) issue_chunk(c + 1);
        compute(c & 1);
    }

    if constexpr (std::is_same<TC, __half>::value) {
        #pragma unroll
        for (int mi = 0; mi < 4; mi++)
            #pragma unroll
            for (int ni = 0; ni < 2; ni++) {
                wmma::fragment<wmma::accumulator, 16, 16, 16, __half> h;
                #pragma unroll
                for (int t = 0; t < h.num_elements; t++)
                    h.x[t] = __float2half(acc[mi][ni].x[t]);
                wmma::store_matrix_sync(
                    C + (size_t)(by*GBM + wm + mi*16)*N + bx*GBN + wn + ni*16,
                    h, N, wmma::mem_row_major);
            }
    } else {
        #pragma unroll
        for (int mi = 0; mi < 4; mi++)
            #pragma unroll
            for (int ni = 0; ni < 2; ni++)
                wmma::store_matrix_sync(
                    C + (size_t)(by*GBM + wm + mi*16)*N + bx*GBN + wn + ni*16,
                    acc[mi][ni], N, wmma::mem_row_major);
    }
}

// ---------------------------------------------------------------------------
// RoPE on fused QKV buffer (which=0 -> Q cols, which=1 -> K cols)
// ---------------------------------------------------------------------------
__global__ void rope_kernel(__half* __restrict__ qkv)
{
    const int total = B * N_SEQ * HEADS * (ROT/2);
    int idx = blockIdx.x * blockDim.x + threadIdx.x;
    if (idx >= 2*total) return;
    const int which = (idx >= total);
    int t = idx - which*total;
    const int i   = t & 15;  t >>= 4;
    const int h   = t & 15;  t >>= 4;
    const int pos = t & (N_SEQ-1); t >>= 11;
    const int b   = t;

    const float inv_freq = powf(10000.f, -(float)(2*i) / (float)ROT);
    const float ang = (float)pos * inv_freq;
    float s, c;
    sincosf(ang, &s, &c);

    __half* base = qkv + ((size_t)(b*N_SEQ + pos)) * QKV_LD
                       + which*INNER + h*DH;
    const float x1 = __half2float(base[2*i]);
    const float x2 = __half2float(base[2*i+1]);
    base[2*i]   = __float2half(x1*c - x2*s);
    base[2*i+1] = __float2half(x2*c + x1*s);
}

// ---------------------------------------------------------------------------
// Flash attention (R12/R13 structure): raw mma.sync, 32 q-rows/warp, 2-stage
// cp.async K/V; P = 2^S via ex2.approx.f32 (fp32 precision, R13 numerics).
// Reads fused QKV buffer: Q at col 0, K at col 1024, V at col 2048.
// ---------------------------------------------------------------------------
#define AQ   256
#define AK   64
#define ALD  72
#define OFF_QS 0
#define KV_SZ (AK*ALD)                  // 4608
#define OFF_K0 (AQ*ALD)                 // 18432
#define OFF_K1 (OFF_K0 + KV_SZ)
#define OFF_V0 (OFF_K1 + KV_SZ)
#define OFF_V1 (OFF_V0 + KV_SZ)
#define ATTN_H (OFF_V1 + KV_SZ)         // 36864 halfs
#define ATTN_SMEM (ATTN_H*2)            // 73728 B

__global__ __launch_bounds__(256, 2)
void attn_kernel(const __half* __restrict__ qkv, __half* __restrict__ out)
{
    extern __shared__ __half smh[];
    const uint32_t smbase = smem_u32(smh);

    const int bh = blockIdx.x;
    const int b  = bh >> 4;
    const int h  = bh & 15;
    const int qt = blockIdx.y;
    const int tid  = threadIdx.x;
    const int w    = tid >> 5;
    const int lane = tid & 31;
    const int gid  = lane >> 2;
    const int tig  = lane & 3;
    const int mi   = lane >> 3;

    // ---- load Q tile (256x64) from QKV, scaled by SCALE*log2e
    const __half* qbase = qkv + ((size_t)(b*N_SEQ) + qt*AQ) * QKV_LD + h*DH;
    const __half2 sc2 = __floats2half2_rn(SCALE*LOG2E, SCALE*LOG2E);
    #pragma unroll
    for (int s = 0; s < 8; s++) {
        const int f = tid + s*256;
        const int r = f >> 3, g = f & 7;
        uint4 v = *(const uint4*)(qbase + (size_t)r*QKV_LD + g*8);
        __half2* hp = (__half2*)&v;
        #pragma unroll
        for (int j = 0; j < 4; j++) hp[j] = __hmul2(hp[j], sc2);
        *(uint4*)(smh + OFF_QS + r*ALD + g*8) = v;
    }

    const __half* kv_bh = qkv + ((size_t)(b*N_SEQ)) * QKV_LD + INNER + h*DH;
    auto issue_tile = [&](int kt) {
        const int p = kt & 1;
        const __half* kbase = kv_bh + (size_t)(kt*AK) * QKV_LD;
        const uint32_t Kb = smbase + (uint32_t)((p ? OFF_K1 : OFF_K0) * 2);
        const uint32_t Vb = smbase + (uint32_t)((p ? OFF_V1 : OFF_V0) * 2);
        #pragma unroll
        for (int s = 0; s < 2; s++) {
            const int f = tid + s*256;
            const int r = f >> 3, g = f & 7;
            const uint32_t off = (uint32_t)((r*ALD + g*8) * 2);
            cp16(Kb + off, kbase + (size_t)r*QKV_LD + g*8);
            cp16(Vb + off, kbase + INNER + (size_t)r*QKV_LD + g*8);
        }
        cp_commit();
    };

    issue_tile(0);
    __syncthreads();

    uint32_t qa[2][4][4];
    #pragma unroll
    for (int m = 0; m < 2; m++) {
        const int qrow = w*32 + m*16 + (mi & 1)*8 + (lane & 7);
        #pragma unroll
        for (int kk = 0; kk < 4; kk++) {
            const uint32_t a = smbase +
                (uint32_t)((OFF_QS + qrow*ALD + kk*16 + (mi >> 1)*8) * 2);
            ldsm_x4(qa[m][kk][0], qa[m][kk][1], qa[m][kk][2], qa[m][kk][3], a);
        }
    }

    float o[2][8][4];
    #pragma unroll
    for (int m = 0; m < 2; m++)
        #pragma unroll
        for (int nt = 0; nt < 8; nt++)
            #pragma unroll
            for (int e = 0; e < 4; e++) o[m][nt][e] = 0.f;
    float lsum[2][2];
    lsum[0][0] = lsum[0][1] = lsum[1][0] = lsum[1][1] = 0.f;

    const int krow_base = ((mi >> 1) << 3) + (lane & 7);
    const int kcol_off  = (mi & 1) * 8;
    const int vrow_base = ((mi & 1) << 3) + (lane & 7);
    const int vcol_off  = (mi >> 1) * 8;

    const int NT = N_SEQ/AK;   // 32
    for (int kt = 0; kt < NT; kt++) {
        const int p = kt & 1;
        cp_wait<0>();
        __syncthreads();
        if (kt + 1 < NT) issue_tile(kt + 1);

        const uint32_t Kb = smbase + (uint32_t)((p ? OFF_K1 : OFF_K0) * 2);
        const uint32_t Vb = smbase + (uint32_t)((p ? OFF_V1 : OFF_V0) * 2);

        #pragma unroll
        for (int jc = 0; jc < 4; jc++) {
            float sa0[4] = {0.f,0.f,0.f,0.f};
            float sa1[4] = {0.f,0.f,0.f,0.f};
            float sb0[4] = {0.f,0.f,0.f,0.f};
            float sb1[4] = {0.f,0.f,0.f,0.f};
            const int krow = jc*16 + krow_base;
            #pragma unroll
            for (int kk = 0; kk < 4; kk++) {
                uint32_t b0, b1, b2, b3;
                ldsm_x4(b0, b1, b2, b3,
                        Kb + (uint32_t)((krow*ALD + kk*16 + kcol_off) * 2));
                mma16816(sa0, qa[0][kk], b0, b1);
                mma16816(sa1, qa[0][kk], b2, b3);
                mma16816(sb0, qa[1][kk], b0, b1);
                mma16816(sb1, qa[1][kk], b2, b3);
            }
            // ---- P = 2^S: fp32 ex2 on accumulator values, pack to half
            uint32_t pa[2][4];
            {
                const float e00 = ex2f(sa0[0]), e01 = ex2f(sa0[1]);
                const float e02 = ex2f(sa0[2]), e03 = ex2f(sa0[3]);
                const float e10 = ex2f(sa1[0]), e11 = ex2f(sa1[1]);
                const float e12 = ex2f(sa1[2]), e13 = ex2f(sa1[3]);
                pa[0][0] = f2h2(e00, e01);
                pa[0][1] = f2h2(e02, e03);
                pa[0][2] = f2h2(e10, e11);
                pa[0][3] = f2h2(e12, e13);
                lsum[0][0] += (e00 + e01) + (e10 + e11);
                lsum[0][1] += (e02 + e03) + (e12 + e13);
            }
            {
                const float e00 = ex2f(sb0[0]), e01 = ex2f(sb0[1]);
                const float e02 = ex2f(sb0[2]), e03 = ex2f(sb0[3]);
                const float e10 = ex2f(sb1[0]), e11 = ex2f(sb1[1]);
                const float e12 = ex2f(sb1[2]), e13 = ex2f(sb1[3]);
                pa[1][0] = f2h2(e00, e01);
                pa[1][1] = f2h2(e02, e03);
                pa[1][2] = f2h2(e10, e11);
                pa[1][3] = f2h2(e12, e13);
                lsum[1][0] += (e00 + e01) + (e10 + e11);
                lsum[1][1] += (e02 + e03) + (e12 + e13);
            }
            const int vrow = jc*16 + vrow_base;
            #pragma unroll
            for (int vp = 0; vp < 4; vp++) {
                uint32_t v0, v1, v2, v3;
                ldsm_x4_t(v0, v1, v2, v3,
                          Vb + (uint32_t)((vrow*ALD + vp*16 + vcol_off) * 2));
                mma16816(o[0][2*vp],   pa[0], v0, v1);
                mma16816(o[0][2*vp+1], pa[0], v2, v3);
                mma16816(o[1][2*vp],   pa[1], v0, v1);
                mma16816(o[1][2*vp+1], pa[1], v2, v3);
            }
        }
    }

    #pragma unroll
    for (int m = 0; m < 2; m++) {
        float l0 = lsum[m][0], l1 = lsum[m][1];
        l0 += __shfl_xor_sync(0xFFFFFFFFu, l0, 1);
        l0 += __shfl_xor_sync(0xFFFFFFFFu, l0, 2);
        l1 += __shfl_xor_sync(0xFFFFFFFFu, l1, 1);
        l1 += __shfl_xor_sync(0xFFFFFFFFu, l1, 2);
        const float inv0 = 1.f / l0;
        const float inv1 = 1.f / l1;

        const int r0 = qt*AQ + w*32 + m*16 + gid;
        __half* ob0 = out + ((size_t)(b*N_SEQ) + r0) * INNER + h*DH + tig*2;
        __half* ob1 = ob0 + (size_t)8 * INNER;
        #pragma unroll
        for (int nt = 0; nt < 8; nt++) {
            *(uint32_t*)(ob0 + nt*8) = f2h2(o[m][nt][0]*inv0, o[m][nt][1]*inv0);
            *(uint32_t*)(ob1 + nt*8) = f2h2(o[m][nt][2]*inv1, o[m][nt][3]*inv1);
        }
    }
}

// ---------------------------------------------------------------------------
// launch
// ---------------------------------------------------------------------------
extern "C" void kernel_launch(void* const* d_in, const int* in_sizes, int n_in,
                              void* d_out, int out_size)
{
    const float* queries = (const float*)d_in[0];
    const float* Wq      = (const float*)d_in[1];
    const float* Wkv     = (const float*)d_in[2];
    const float* Wout    = (const float*)d_in[3];
    const float* bout    = (const float*)d_in[4];
    float* out = (float*)d_out;

    __half *qkv, *attnp, *qh, *wqkv, *wo;
    cudaGetSymbolAddress((void**)&qkv,   g_qkv);
    cudaGetSymbolAddress((void**)&attnp, g_attn);
    cudaGetSymbolAddress((void**)&qh,    g_qh);
    cudaGetSymbolAddress((void**)&wqkv,  g_wqkv);
    cudaGetSymbolAddress((void**)&wo,    g_wo);

    static bool attr_set = false;
    if (!attr_set) {
        cudaFuncSetAttribute(attn_kernel,
                             cudaFuncAttributeMaxDynamicSharedMemorySize,
                             (int)ATTN_SMEM);
        cudaFuncSetAttribute(gemm_f16_kernel<__half>,
                             cudaFuncAttributeMaxDynamicSharedMemorySize,
                             GEMM_SMEM);
        cudaFuncSetAttribute(gemm_f16_kernel<float>,
                             cudaFuncAttributeMaxDynamicSharedMemorySize,
                             GEMM_SMEM);
        attr_set = true;
    }

    const int M = B * N_SEQ;  // 8192

    // ---- one-shot fp32 -> fp16 conversions (weights concatenated: Wq|Wkv)
    {
        const int nq8 = (M * D_MODEL) / 8;
        f2h_kernel<<<(nq8 + 255)/256, 256>>>(queries, qh, nq8);
        const int nwq8 = (D_MODEL * INNER) / 8;
        f2h_cols_kernel<<<(nwq8 + 255)/256, 256>>>(Wq, wqkv, INNER, QKV_LD, nwq8);
        const int nwkv8 = (D_MODEL * 2*INNER) / 8;
        f2h_cols_kernel<<<(nwkv8 + 255)/256, 256>>>(Wkv, wqkv + INNER,
                                                    2*INNER, QKV_LD, nwkv8);
        const int nwo8 = (INNER * D_MODEL) / 8;
        f2h_kernel<<<(nwo8 + 255)/256, 256>>>(Wout, wo, nwo8);
    }

    // QKV = queries @ [Wq|Wkv]  -> half [8192, 3072]
    {
        dim3 grid(QKV_LD/GBN, M/GBM);   // 24 x 64 = 1536 CTAs
        gemm_f16_kernel<__half><<<grid, 256, GEMM_SMEM>>>(
            qh, wqkv, nullptr, qkv, M, QKV_LD, D_MODEL);
    }
    // RoPE (in-place on Q and K column blocks)
    {
        const int total = 2 * B * N_SEQ * HEADS * (ROT/2);
        rope_kernel<<<(total + 255)/256, 256>>>(qkv);
    }
    // attention -> half
    {
        dim3 grid(B*HEADS, N_SEQ/AQ);
        attn_kernel<<<grid, 256, ATTN_SMEM>>>(qkv, attnp);
    }
    // out = attn @ Wout + bout -> float
    {
        dim3 grid(D_MODEL/GBN, M/GBM);
        gemm_f16_kernel<float><<<grid, 256, GEMM_SMEM>>>(
            attnp, wo, bout, out, M, D_MODEL, INNER);
    }
}

// round 16
// speedup vs baseline: 1.0666x; 1.0078x over previous
#include <cuda_runtime.h>
#include <cuda_fp16.h>
#include <mma.h>
#include <cstdint>
#include <math.h>
#include <type_traits>

using namespace nvcuda;

// ---------------------------------------------------------------------------
// Problem constants
// ---------------------------------------------------------------------------
#define B       4
#define N_SEQ   2048
#define D_MODEL 1024
#define HEADS   16
#define DH      64
#define INNER   (HEADS*DH)  // 1024
#define ROT     32
#define SCALE   0.125f
#define LOG2E   1.4426950408889634f
#define QKV_LD  (3*INNER)   // 3072: fused Q|K|V row stride

// ---------------------------------------------------------------------------
// Scratch (static device globals — no allocation allowed)
// ---------------------------------------------------------------------------
__device__ __half g_qkv [(size_t)B*N_SEQ*QKV_LD];     // 48 MB  [8192][3072] Q|K|V
__device__ __half g_attn[(size_t)B*N_SEQ*INNER];      // 16 MB
__device__ __half g_qh  [(size_t)B*N_SEQ*D_MODEL];    // 16 MB queries in half
__device__ __half g_wqkv[(size_t)D_MODEL*QKV_LD];     // 6 MB  [1024][3072] Wq|Wkv
__device__ __half g_wo  [(size_t)INNER*D_MODEL];      // 2 MB

__device__ __forceinline__ uint32_t f2h2(float a, float b) {
    __half2 h = __floats2half2_rn(a, b);
    return *(uint32_t*)&h;
}
__device__ __forceinline__ float ex2f(float x) {
    float r;
    asm("ex2.approx.f32 %0, %1;" : "=f"(r) : "f"(x));
    return r;
}
__device__ __forceinline__ uint32_t smem_u32(const void* p) {
    uint32_t a;
    asm("{ .reg .u64 t; cvta.to.shared.u64 t, %1; cvt.u32.u64 %0, t; }"
        : "=r"(a) : "l"(p));
    return a;
}
__device__ __forceinline__ void ldsm_x4(uint32_t& r0, uint32_t& r1,
                                        uint32_t& r2, uint32_t& r3, uint32_t a) {
    asm volatile("ldmatrix.sync.aligned.m8n8.x4.shared.b16 {%0,%1,%2,%3}, [%4];"
                 : "=r"(r0), "=r"(r1), "=r"(r2), "=r"(r3) : "r"(a));
}
__device__ __forceinline__ void ldsm_x4_t(uint32_t& r0, uint32_t& r1,
                                          uint32_t& r2, uint32_t& r3, uint32_t a) {
    asm volatile("ldmatrix.sync.aligned.m8n8.x4.trans.shared.b16 {%0,%1,%2,%3}, [%4];"
                 : "=r"(r0), "=r"(r1), "=r"(r2), "=r"(r3) : "r"(a));
}
__device__ __forceinline__ void mma16816(float* c, const uint32_t* a,
                                         uint32_t b0, uint32_t b1) {
    asm volatile(
        "mma.sync.aligned.m16n8k16.row.col.f32.f16.f16.f32 "
        "{%0,%1,%2,%3}, {%4,%5,%6,%7}, {%8,%9}, {%0,%1,%2,%3};"
        : "+f"(c[0]), "+f"(c[1]), "+f"(c[2]), "+f"(c[3])
        : "r"(a[0]), "r"(a[1]), "r"(a[2]), "r"(a[3]), "r"(b0), "r"(b1));
}
__device__ __forceinline__ void cp16(uint32_t dst, const void* src) {
    asm volatile("cp.async.cg.shared.global [%0], [%1], 16;"
                 :: "r"(dst), "l"(src) : "memory");
}
__device__ __forceinline__ void cp_commit() {
    asm volatile("cp.async.commit_group;" ::: "memory");
}
template<int N>
__device__ __forceinline__ void cp_wait() {
    asm volatile("cp.async.wait_group %0;" :: "n"(N) : "memory");
}

// ---------------------------------------------------------------------------
// fp32 -> fp16 bulk convert; contiguous dst
// ---------------------------------------------------------------------------
__global__ void f2h_kernel(const float* __restrict__ src, __half* __restrict__ dst,
                           int n8)
{
    const int i = blockIdx.x * blockDim.x + threadIdx.x;
    if (i >= n8) return;
    const float4 a = ((const float4*)src)[2*i];
    const float4 b = ((const float4*)src)[2*i + 1];
    uint4 h;
    h.x = f2h2(a.x, a.y);
    h.y = f2h2(a.z, a.w);
    h.z = f2h2(b.x, b.y);
    h.w = f2h2(b.z, b.w);
    ((uint4*)dst)[i] = h;
}

// fp32 [rows, srcN] -> fp16 into dst with row stride dstLD (column-block concat)
__global__ void f2h_cols_kernel(const float* __restrict__ src, __half* __restrict__ dst,
                                int srcN, int dstLD, int n8)
{
    const int i = blockIdx.x * blockDim.x + threadIdx.x;
    if (i >= n8) return;
    const int gpr = srcN >> 3;           // 8-elem groups per row
    const int r = i / gpr, c8 = i - r*gpr;
    const float4 a = *(const float4*)(src + (size_t)r*srcN + c8*8);
    const float4 b = *(const float4*)(src + (size_t)r*srcN + c8*8 + 4);
    uint4 h;
    h.x = f2h2(a.x, a.y);
    h.y = f2h2(a.z, a.w);
    h.z = f2h2(b.x, b.y);
    h.w = f2h2(b.z, b.w);
    *(uint4*)(dst + (size_t)r*dstLD + c8*8) = h;
}

// ---------------------------------------------------------------------------
// fp16 wmma GEMM: C = A @ B (+bias via accumulator init); A,B half in gmem.
// Tile 128x128x64, 256 threads, 2 CTAs/SM, 2-stage cp.async pipeline. (R15)
// ---------------------------------------------------------------------------
#define GBM 128
#define GBN 128
#define GBK 64
#define A_LDH 72      // 64 + 8 pad
#define B_LDH 136     // 128 + 8 pad
#define STAGE_H (GBM*A_LDH + GBK*B_LDH)            // 17920 halfs
#define GEMM_BIAS_OFF (2*STAGE_H)
#define GEMM_SMEM (2*STAGE_H*2 + 16*GBN*4)         // 79872 B

template<typename TC>
__global__ __launch_bounds__(256, 2)
void gemm_f16_kernel(const __half* __restrict__ A, const __half* __restrict__ Bm,
                     const float* __restrict__ bias, TC* __restrict__ C,
                     int M, int N, int K)
{
    extern __shared__ __half smh[];
    const uint32_t smbase = smem_u32(smh);
    const int tid = threadIdx.x;
    const int wid = tid >> 5;
    const int bx = blockIdx.x;
    const int by = blockIdx.y;
    const int wm = (wid & 1) * 64;
    const int wn = (wid >> 1) * 32;

    float* biasRep = (float*)(smh + GEMM_BIAS_OFF);   // [16][GBN]
    if (bias) {
        const float bval = __ldg(bias + bx*GBN + (tid & 127));
        biasRep[(tid >> 7) * GBN + (tid & 127)] = bval;
        #pragma unroll
        for (int rr = 2; rr < 16; rr += 2)
            biasRep[(rr + (tid >> 7)) * GBN + (tid & 127)] = bval;
    }

    wmma::fragment<wmma::accumulator, 16, 16, 16, float> acc[4][2];

    const __half* Ag = A + (size_t)(by*GBM) * K;
    const __half* Bg = Bm + (size_t)bx * GBN;

    auto issue_chunk = [&](int c) {
        const int p = c & 1;
        const int k0 = c * GBK;
        const uint32_t As = smbase + (uint32_t)(p*STAGE_H)*2;
        const uint32_t Bs = As + (uint32_t)(GBM*A_LDH)*2;
        #pragma unroll
        for (int s = 0; s < 4; s++) {
            const int f = tid + s*256;           // 1024 x 16B over A tile
            const int r = f >> 3, g = f & 7;
            cp16(As + (uint32_t)((r*A_LDH + g*8)*2),
                 Ag + (size_t)r*K + k0 + g*8);
        }
        #pragma unroll
        for (int s = 0; s < 4; s++) {
            const int f = tid + s*256;           // 1024 x 16B over B tile
            const int r = f >> 4, g = f & 15;
            cp16(Bs + (uint32_t)((r*B_LDH + g*8)*2),
                 Bg + (size_t)(k0 + r)*N + g*8);
        }
        cp_commit();
    };
    auto compute = [&](int p) {
        const __half* As = smh + p*STAGE_H;
        const __half* Bs = As + GBM*A_LDH;
        #pragma unroll
        for (int ks = 0; ks < 4; ks++) {
            wmma::fragment<wmma::matrix_a, 16, 16, 16, __half, wmma::row_major> af[4];
            wmma::fragment<wmma::matrix_b, 16, 16, 16, __half, wmma::row_major> bf[2];
            #pragma unroll
            for (int mi = 0; mi < 4; mi++)
                wmma::load_matrix_sync(af[mi], As + (wm + mi*16)*A_LDH + ks*16, A_LDH);
            #pragma unroll
            for (int ni = 0; ni < 2; ni++)
                wmma::load_matrix_sync(bf[ni], Bs + (ks*16)*B_LDH + wn + ni*16, B_LDH);
            #pragma unroll
            for (int mi = 0; mi < 4; mi++)
                #pragma unroll
                for (int ni = 0; ni < 2; ni++)
                    wmma::mma_sync(acc[mi][ni], af[mi], bf[ni], acc[mi][ni]);
        }
    };

    const int NC = K / GBK;   // 16
    issue_chunk(0);
    cp_wait<0>();
    __syncthreads();          // chunk0 + biasRep visible

    if (bias) {
        #pragma unroll
        for (int mi = 0; mi < 4; mi++)
            #pragma unroll
            for (int ni = 0; ni < 2; ni++)
                wmma::load_matrix_sync(acc[mi][ni], biasRep + wn + ni*16, GBN,
                                       wmma::mem_row_major);
    } else {
        #pragma unroll
        for (int mi = 0; mi < 4; mi++)
            #pragma unroll
            for (int ni = 0; ni < 2; ni++)
                wmma::fill_fragment(acc[mi][ni], 0.f);
    }

    for (int c = 0; c < NC; c++) {
        if (c > 0) {
            cp_wait<0>();
            __syncthreads();
        }
        if (c + 1 < NC) issue_chunk(c + 1);
        compute(c & 1);
    }

    if constexpr (std::is_same<TC, __half>::value) {
        #pragma unroll
        for (int mi = 0; mi < 4; mi++)
            #pragma unroll
            for (int ni = 0; ni < 2; ni++) {
                wmma::fragment<wmma::accumulator, 16, 16, 16, __half> h;
                #pragma unroll
                for (int t = 0; t < h.num_elements; t++)
                    h.x[t] = __float2half(acc[mi][ni].x[t]);
                wmma::store_matrix_sync(
                    C + (size_t)(by*GBM + wm + mi*16)*N + bx*GBN + wn + ni*16,
                    h, N, wmma::mem_row_major);
            }
    } else {
        #pragma unroll
        for (int mi = 0; mi < 4; mi++)
            #pragma unroll
            for (int ni = 0; ni < 2; ni++)
                wmma::store_matrix_sync(
                    C + (size_t)(by*GBM + wm + mi*16)*N + bx*GBN + wn + ni*16,
                    acc[mi][ni], N, wmma::mem_row_major);
    }
}

// ---------------------------------------------------------------------------
// RoPE on fused QKV buffer (which=0 -> Q cols, which=1 -> K cols)
// ---------------------------------------------------------------------------
__global__ void rope_kernel(__half* __restrict__ qkv)
{
    const int total = B * N_SEQ * HEADS * (ROT/2);
    int idx = blockIdx.x * blockDim.x + threadIdx.x;
    if (idx >= 2*total) return;
    const int which = (idx >= total);
    int t = idx - which*total;
    const int i   = t & 15;  t >>= 4;
    const int h   = t & 15;  t >>= 4;
    const int pos = t & (N_SEQ-1); t >>= 11;
    const int b   = t;

    const float inv_freq = powf(10000.f, -(float)(2*i) / (float)ROT);
    const float ang = (float)pos * inv_freq;
    float s, c;
    sincosf(ang, &s, &c);

    __half* base = qkv + ((size_t)(b*N_SEQ + pos)) * QKV_LD
                       + which*INNER + h*DH;
    const float x1 = __half2float(base[2*i]);
    const float x2 = __half2float(base[2*i+1]);
    base[2*i]   = __float2half(x1*c - x2*s);
    base[2*i+1] = __float2half(x2*c + x1*s);
}

// ---------------------------------------------------------------------------
// Flash attention: raw mma.sync, 32 q-rows/warp, AK=128 kv tiles (16 iters,
// 8 key-chunks unrolled per body -> half the pipeline barriers, 2x scheduling
// window for MUFU/tensor overlap). 2-stage cp.async; P = 2^S via ex2.approx.f32.
// Key processing order identical to R15 -> bit-identical numerics.
// Reads fused QKV buffer: Q at col 0, K at col 1024, V at col 2048.
// ---------------------------------------------------------------------------
#define AQ   256
#define AK   128
#define ALD  72
#define OFF_QS 0
#define KV_SZ (AK*ALD)                  // 9216
#define OFF_K0 (AQ*ALD)                 // 18432
#define OFF_K1 (OFF_K0 + KV_SZ)         // 27648
#define OFF_V0 (OFF_K1 + KV_SZ)         // 36864
#define OFF_V1 (OFF_V0 + KV_SZ)         // 46080
#define ATTN_H (OFF_V1 + KV_SZ)         // 55296 halfs
#define ATTN_SMEM (ATTN_H*2)            // 110592 B; x2 CTAs = 221184 < 228KB

__global__ __launch_bounds__(256, 2)
void attn_kernel(const __half* __restrict__ qkv, __half* __restrict__ out)
{
    extern __shared__ __half smh[];
    const uint32_t smbase = smem_u32(smh);

    const int bh = blockIdx.x;
    const int b  = bh >> 4;
    const int h  = bh & 15;
    const int qt = blockIdx.y;
    const int tid  = threadIdx.x;
    const int w    = tid >> 5;
    const int lane = tid & 31;
    const int gid  = lane >> 2;
    const int tig  = lane & 3;
    const int mi   = lane >> 3;

    // ---- load Q tile (256x64) from QKV, scaled by SCALE*log2e
    const __half* qbase = qkv + ((size_t)(b*N_SEQ) + qt*AQ) * QKV_LD + h*DH;
    const __half2 sc2 = __floats2half2_rn(SCALE*LOG2E, SCALE*LOG2E);
    #pragma unroll
    for (int s = 0; s < 8; s++) {
        const int f = tid + s*256;
        const int r = f >> 3, g = f & 7;
        uint4 v = *(const uint4*)(qbase + (size_t)r*QKV_LD + g*8);
        __half2* hp = (__half2*)&v;
        #pragma unroll
        for (int j = 0; j < 4; j++) hp[j] = __hmul2(hp[j], sc2);
        *(uint4*)(smh + OFF_QS + r*ALD + g*8) = v;
    }

    const __half* kv_bh = qkv + ((size_t)(b*N_SEQ)) * QKV_LD + INNER + h*DH;
    // issue one 128-key kv tile into stage kt&1 (single cp.async commit group)
    auto issue_tile = [&](int kt) {
        const int p = kt & 1;
        const __half* kbase = kv_bh + (size_t)(kt*AK) * QKV_LD;
        const uint32_t Kb = smbase + (uint32_t)((p ? OFF_K1 : OFF_K0) * 2);
        const uint32_t Vb = smbase + (uint32_t)((p ? OFF_V1 : OFF_V0) * 2);
        #pragma unroll
        for (int s = 0; s < 4; s++) {
            const int f = tid + s*256;       // 1024 x 16B per matrix
            const int r = f >> 3, g = f & 7;
            const uint32_t off = (uint32_t)((r*ALD + g*8) * 2);
            cp16(Kb + off, kbase + (size_t)r*QKV_LD + g*8);
            cp16(Vb + off, kbase + INNER + (size_t)r*QKV_LD + g*8);
        }
        cp_commit();
    };

    issue_tile(0);
    __syncthreads();   // Q visible

    uint32_t qa[2][4][4];
    #pragma unroll
    for (int m = 0; m < 2; m++) {
        const int qrow = w*32 + m*16 + (mi & 1)*8 + (lane & 7);
        #pragma unroll
        for (int kk = 0; kk < 4; kk++) {
            const uint32_t a = smbase +
                (uint32_t)((OFF_QS + qrow*ALD + kk*16 + (mi >> 1)*8) * 2);
            ldsm_x4(qa[m][kk][0], qa[m][kk][1], qa[m][kk][2], qa[m][kk][3], a);
        }
    }

    float o[2][8][4];
    #pragma unroll
    for (int m = 0; m < 2; m++)
        #pragma unroll
        for (int nt = 0; nt < 8; nt++)
            #pragma unroll
            for (int e = 0; e < 4; e++) o[m][nt][e] = 0.f;
    float lsum[2][2];
    lsum[0][0] = lsum[0][1] = lsum[1][0] = lsum[1][1] = 0.f;

    const int krow_base = ((mi >> 1) << 3) + (lane & 7);
    const int kcol_off  = (mi & 1) * 8;
    const int vrow_base = ((mi & 1) << 3) + (lane & 7);
    const int vcol_off  = (mi >> 1) * 8;

    const int NT = N_SEQ/AK;   // 16
    for (int kt = 0; kt < NT; kt++) {
        const int p = kt & 1;
        cp_wait<0>();
        __syncthreads();
        if (kt + 1 < NT) issue_tile(kt + 1);

        const uint32_t Kb = smbase + (uint32_t)((p ? OFF_K1 : OFF_K0) * 2);
        const uint32_t Vb = smbase + (uint32_t)((p ? OFF_V1 : OFF_V0) * 2);

        #pragma unroll
        for (int jc = 0; jc < 8; jc++) {     // 16-key chunks (8 per tile)
            float sa0[4] = {0.f,0.f,0.f,0.f};
            float sa1[4] = {0.f,0.f,0.f,0.f};
            float sb0[4] = {0.f,0.f,0.f,0.f};
            float sb1[4] = {0.f,0.f,0.f,0.f};
            const int krow = jc*16 + krow_base;
            #pragma unroll
            for (int kk = 0; kk < 4; kk++) {
                uint32_t b0, b1, b2, b3;
                ldsm_x4(b0, b1, b2, b3,
                        Kb + (uint32_t)((krow*ALD + kk*16 + kcol_off) * 2));
                mma16816(sa0, qa[0][kk], b0, b1);
                mma16816(sa1, qa[0][kk], b2, b3);
                mma16816(sb0, qa[1][kk], b0, b1);
                mma16816(sb1, qa[1][kk], b2, b3);
            }
            // ---- P = 2^S: fp32 ex2 on accumulator values, pack to half
            uint32_t pa[2][4];
            {
                const float e00 = ex2f(sa0[0]), e01 = ex2f(sa0[1]);
                const float e02 = ex2f(sa0[2]), e03 = ex2f(sa0[3]);
                const float e10 = ex2f(sa1[0]), e11 = ex2f(sa1[1]);
                const float e12 = ex2f(sa1[2]), e13 = ex2f(sa1[3]);
                pa[0][0] = f2h2(e00, e01);
                pa[0][1] = f2h2(e02, e03);
                pa[0][2] = f2h2(e10, e11);
                pa[0][3] = f2h2(e12, e13);
                lsum[0][0] += (e00 + e01) + (e10 + e11);
                lsum[0][1] += (e02 + e03) + (e12 + e13);
            }
            {
                const float e00 = ex2f(sb0[0]), e01 = ex2f(sb0[1]);
                const float e02 = ex2f(sb0[2]), e03 = ex2f(sb0[3]);
                const float e10 = ex2f(sb1[0]), e11 = ex2f(sb1[1]);
                const float e12 = ex2f(sb1[2]), e13 = ex2f(sb1[3]);
                pa[1][0] = f2h2(e00, e01);
                pa[1][1] = f2h2(e02, e03);
                pa[1][2] = f2h2(e10, e11);
                pa[1][3] = f2h2(e12, e13);
                lsum[1][0] += (e00 + e01) + (e10 + e11);
                lsum[1][1] += (e02 + e03) + (e12 + e13);
            }
            const int vrow = jc*16 + vrow_base;
            #pragma unroll
            for (int vp = 0; vp < 4; vp++) {
                uint32_t v0, v1, v2, v3;
                ldsm_x4_t(v0, v1, v2, v3,
                          Vb + (uint32_t)((vrow*ALD + vp*16 + vcol_off) * 2));
                mma16816(o[0][2*vp],   pa[0], v0, v1);
                mma16816(o[0][2*vp+1], pa[0], v2, v3);
                mma16816(o[1][2*vp],   pa[1], v0, v1);
                mma16816(o[1][2*vp+1], pa[1], v2, v3);
            }
        }
    }

    #pragma unroll
    for (int m = 0; m < 2; m++) {
        float l0 = lsum[m][0], l1 = lsum[m][1];
        l0 += __shfl_xor_sync(0xFFFFFFFFu, l0, 1);
        l0 += __shfl_xor_sync(0xFFFFFFFFu, l0, 2);
        l1 += __shfl_xor_sync(0xFFFFFFFFu, l1, 1);
        l1 += __shfl_xor_sync(0xFFFFFFFFu, l1, 2);
        const float inv0 = 1.f / l0;
        const float inv1 = 1.f / l1;

        const int r0 = qt*AQ + w*32 + m*16 + gid;
        __half* ob0 = out + ((size_t)(b*N_SEQ) + r0) * INNER + h*DH + tig*2;
        __half* ob1 = ob0 + (size_t)8 * INNER;
        #pragma unroll
        for (int nt = 0; nt < 8; nt++) {
            *(uint32_t*)(ob0 + nt*8) = f2h2(o[m][nt][0]*inv0, o[m][nt][1]*inv0);
            *(uint32_t*)(ob1 + nt*8) = f2h2(o[m][nt][2]*inv1, o[m][nt][3]*inv1);
        }
    }
}

// ---------------------------------------------------------------------------
// launch
// ---------------------------------------------------------------------------
extern "C" void kernel_launch(void* const* d_in, const int* in_sizes, int n_in,
                              void* d_out, int out_size)
{
    const float* queries = (const float*)d_in[0];
    const float* Wq      = (const float*)d_in[1];
    const float* Wkv     = (const float*)d_in[2];
    const float* Wout    = (const float*)d_in[3];
    const float* bout    = (const float*)d_in[4];
    float* out = (float*)d_out;

    __half *qkv, *attnp, *qh, *wqkv, *wo;
    cudaGetSymbolAddress((void**)&qkv,   g_qkv);
    cudaGetSymbolAddress((void**)&attnp, g_attn);
    cudaGetSymbolAddress((void**)&qh,    g_qh);
    cudaGetSymbolAddress((void**)&wqkv,  g_wqkv);
    cudaGetSymbolAddress((void**)&wo,    g_wo);

    static bool attr_set = false;
    if (!attr_set) {
        cudaFuncSetAttribute(attn_kernel,
                             cudaFuncAttributeMaxDynamicSharedMemorySize,
                             (int)ATTN_SMEM);
        cudaFuncSetAttribute(gemm_f16_kernel<__half>,
                             cudaFuncAttributeMaxDynamicSharedMemorySize,
                             GEMM_SMEM);
        cudaFuncSetAttribute(gemm_f16_kernel<float>,
                             cudaFuncAttributeMaxDynamicSharedMemorySize,
                             GEMM_SMEM);
        attr_set = true;
    }

    const int M = B * N_SEQ;  // 8192

    // ---- one-shot fp32 -> fp16 conversions (weights concatenated: Wq|Wkv)
    {
        const int nq8 = (M * D_MODEL) / 8;
        f2h_kernel<<<(nq8 + 255)/256, 256>>>(queries, qh, nq8);
        const int nwq8 = (D_MODEL * INNER) / 8;
        f2h_cols_kernel<<<(nwq8 + 255)/256, 256>>>(Wq, wqkv, INNER, QKV_LD, nwq8);
        const int nwkv8 = (D_MODEL * 2*INNER) / 8;
        f2h_cols_kernel<<<(nwkv8 + 255)/256, 256>>>(Wkv, wqkv + INNER,
                                                    2*INNER, QKV_LD, nwkv8);
        const int nwo8 = (INNER * D_MODEL) / 8;
        f2h_kernel<<<(nwo8 + 255)/256, 256>>>(Wout, wo, nwo8);
    }

    // QKV = queries @ [Wq|Wkv]  -> half [8192, 3072]
    {
        dim3 grid(QKV_LD/GBN, M/GBM);   // 24 x 64 = 1536 CTAs
        gemm_f16_kernel<__half><<<grid, 256, GEMM_SMEM>>>(
            qh, wqkv, nullptr, qkv, M, QKV_LD, D_MODEL);
    }
    // RoPE (in-place on Q and K column blocks)
    {
        const int total = 2 * B * N_SEQ * HEADS * (ROT/2);
        rope_kernel<<<(total + 255)/256, 256>>>(qkv);
    }
    // attention -> half
    {
        dim3 grid(B*HEADS, N_SEQ/AQ);
        attn_kernel<<<grid, 256, ATTN_SMEM>>>(qkv, attnp);
    }
    // out = attn @ Wout + bout -> float
    {
        dim3 grid(D_MODEL/GBN, M/GBM);
        gemm_f16_kernel<float><<<grid, 256, GEMM_SMEM>>>(
            attnp, wo, bout, out, M, D_MODEL, INNER);
    }
}

// round 17
// speedup vs baseline: 1.0868x; 1.0189x over previous
#include <cuda_runtime.h>
#include <cuda_fp16.h>
#include <mma.h>
#include <cstdint>
#include <math.h>
#include <type_traits>

using namespace nvcuda;

// ---------------------------------------------------------------------------
// Problem constants
// ---------------------------------------------------------------------------
#define B       4
#define N_SEQ   2048
#define D_MODEL 1024
#define HEADS   16
#define DH      64
#define INNER   (HEADS*DH)  // 1024
#define ROT     32
#define SCALE   0.125f
#define LOG2E   1.4426950408889634f
#define QKV_LD  (3*INNER)   // 3072: fused Q|K|V row stride

// ---------------------------------------------------------------------------
// Scratch (static device globals — no allocation allowed)
// ---------------------------------------------------------------------------
__device__ __half g_qkv [(size_t)B*N_SEQ*QKV_LD];     // 48 MB
__device__ __half g_attn[(size_t)B*N_SEQ*INNER];      // 16 MB
__device__ __half g_qh  [(size_t)B*N_SEQ*D_MODEL];    // 16 MB
__device__ __half g_wqkv[(size_t)D_MODEL*QKV_LD];     // 6 MB
__device__ __half g_wo  [(size_t)INNER*D_MODEL];      // 2 MB

__device__ __forceinline__ uint32_t f2h2(float a, float b) {
    __half2 h = __floats2half2_rn(a, b);
    return *(uint32_t*)&h;
}
__device__ __forceinline__ float ex2f(float x) {
    float r;
    asm("ex2.approx.f32 %0, %1;" : "=f"(r) : "f"(x));
    return r;
}
__device__ __forceinline__ uint32_t smem_u32(const void* p) {
    uint32_t a;
    asm("{ .reg .u64 t; cvta.to.shared.u64 t, %1; cvt.u32.u64 %0, t; }"
        : "=r"(a) : "l"(p));
    return a;
}
__device__ __forceinline__ void ldsm_x4(uint32_t& r0, uint32_t& r1,
                                        uint32_t& r2, uint32_t& r3, uint32_t a) {
    asm volatile("ldmatrix.sync.aligned.m8n8.x4.shared.b16 {%0,%1,%2,%3}, [%4];"
                 : "=r"(r0), "=r"(r1), "=r"(r2), "=r"(r3) : "r"(a));
}
__device__ __forceinline__ void ldsm_x4_t(uint32_t& r0, uint32_t& r1,
                                          uint32_t& r2, uint32_t& r3, uint32_t a) {
    asm volatile("ldmatrix.sync.aligned.m8n8.x4.trans.shared.b16 {%0,%1,%2,%3}, [%4];"
                 : "=r"(r0), "=r"(r1), "=r"(r2), "=r"(r3) : "r"(a));
}
__device__ __forceinline__ void mma16816(float* c, const uint32_t* a,
                                         uint32_t b0, uint32_t b1) {
    asm volatile(
        "mma.sync.aligned.m16n8k16.row.col.f32.f16.f16.f32 "
        "{%0,%1,%2,%3}, {%4,%5,%6,%7}, {%8,%9}, {%0,%1,%2,%3};"
        : "+f"(c[0]), "+f"(c[1]), "+f"(c[2]), "+f"(c[3])
        : "r"(a[0]), "r"(a[1]), "r"(a[2]), "r"(a[3]), "r"(b0), "r"(b1));
}
__device__ __forceinline__ void cp16(uint32_t dst, const void* src) {
    asm volatile("cp.async.cg.shared.global [%0], [%1], 16;"
                 :: "r"(dst), "l"(src) : "memory");
}
__device__ __forceinline__ void cp_commit() {
    asm volatile("cp.async.commit_group;" ::: "memory");
}
template<int N>
__device__ __forceinline__ void cp_wait() {
    asm volatile("cp.async.wait_group %0;" :: "n"(N) : "memory");
}

// ---------------------------------------------------------------------------
// Merged fp32 -> fp16 conversion: 4 segments in one launch.
//   seg0: queries  [8192x1024] -> g_qh      (contiguous)
//   seg1: Wq       [1024x1024] -> g_wqkv cols 0..1023    (stride 3072)
//   seg2: Wkv      [1024x2048] -> g_wqkv cols 1024..3071 (stride 3072)
//   seg3: Wout     [1024x1024] -> g_wo      (contiguous)
// ---------------------------------------------------------------------------
#define N8_Q   ((B*N_SEQ*D_MODEL)/8)        // 1048576
#define N8_WQ  ((D_MODEL*INNER)/8)          // 131072
#define N8_WKV ((D_MODEL*2*INNER)/8)        // 262144
#define N8_WO  ((INNER*D_MODEL)/8)          // 131072
#define N8_ALL (N8_Q + N8_WQ + N8_WKV + N8_WO)

__global__ void f2h_all_kernel(const float* __restrict__ queries,
                               const float* __restrict__ Wq,
                               const float* __restrict__ Wkv,
                               const float* __restrict__ Wout,
                               __half* __restrict__ qh,
                               __half* __restrict__ wqkv,
                               __half* __restrict__ wo)
{
    const int i = blockIdx.x * blockDim.x + threadIdx.x;
    if (i >= N8_ALL) return;
    const float* src;
    __half* dst;
    if (i < N8_Q) {
        src = queries + (size_t)i * 8;
        dst = qh + (size_t)i * 8;
    } else if (i < N8_Q + N8_WQ) {
        const int j = i - N8_Q;
        const int r = j >> 7, c8 = j & 127;          // 1024 cols = 128 groups
        src = Wq + (size_t)r * INNER + c8 * 8;
        dst = wqkv + (size_t)r * QKV_LD + c8 * 8;
    } else if (i < N8_Q + N8_WQ + N8_WKV) {
        const int j = i - (N8_Q + N8_WQ);
        const int r = j >> 8, c8 = j & 255;          // 2048 cols = 256 groups
        src = Wkv + (size_t)r * (2*INNER) + c8 * 8;
        dst = wqkv + (size_t)r * QKV_LD + INNER + c8 * 8;
    } else {
        const int j = i - (N8_Q + N8_WQ + N8_WKV);
        src = Wout + (size_t)j * 8;
        dst = wo + (size_t)j * 8;
    }
    const float4 a = *(const float4*)src;
    const float4 b = *(const float4*)(src + 4);
    uint4 h;
    h.x = f2h2(a.x, a.y);
    h.y = f2h2(a.z, a.w);
    h.z = f2h2(b.x, b.y);
    h.w = f2h2(b.z, b.w);
    *(uint4*)dst = h;
}

// ---------------------------------------------------------------------------
// fp16 wmma GEMM: C = A @ B (+bias via accumulator init). (R15/R16)
// Tile 128x128x64, 256 threads, 2 CTAs/SM, 2-stage cp.async pipeline.
// ---------------------------------------------------------------------------
#define GBM 128
#define GBN 128
#define GBK 64
#define A_LDH 72
#define B_LDH 136
#define STAGE_H (GBM*A_LDH + GBK*B_LDH)            // 17920 halfs
#define GEMM_BIAS_OFF (2*STAGE_H)
#define GEMM_SMEM (2*STAGE_H*2 + 16*GBN*4)         // 79872 B

template<typename TC>
__global__ __launch_bounds__(256, 2)
void gemm_f16_kernel(const __half* __restrict__ A, const __half* __restrict__ Bm,
                     const float* __restrict__ bias, TC* __restrict__ C,
                     int M, int N, int K)
{
    extern __shared__ __half smh[];
    const uint32_t smbase = smem_u32(smh);
    const int tid = threadIdx.x;
    const int wid = tid >> 5;
    const int bx = blockIdx.x;
    const int by = blockIdx.y;
    const int wm = (wid & 1) * 64;
    const int wn = (wid >> 1) * 32;

    float* biasRep = (float*)(smh + GEMM_BIAS_OFF);
    if (bias) {
        const float bval = __ldg(bias + bx*GBN + (tid & 127));
        biasRep[(tid >> 7) * GBN + (tid & 127)] = bval;
        #pragma unroll
        for (int rr = 2; rr < 16; rr += 2)
            biasRep[(rr + (tid >> 7)) * GBN + (tid & 127)] = bval;
    }

    wmma::fragment<wmma::accumulator, 16, 16, 16, float> acc[4][2];

    const __half* Ag = A + (size_t)(by*GBM) * K;
    const __half* Bg = Bm + (size_t)bx * GBN;

    auto issue_chunk = [&](int c) {
        const int p = c & 1;
        const int k0 = c * GBK;
        const uint32_t As = smbase + (uint32_t)(p*STAGE_H)*2;
        const uint32_t Bs = As + (uint32_t)(GBM*A_LDH)*2;
        #pragma unroll
        for (int s = 0; s < 4; s++) {
            const int f = tid + s*256;
            const int r = f >> 3, g = f & 7;
            cp16(As + (uint32_t)((r*A_LDH + g*8)*2),
                 Ag + (size_t)r*K + k0 + g*8);
        }
        #pragma unroll
        for (int s = 0; s < 4; s++) {
            const int f = tid + s*256;
            const int r = f >> 4, g = f & 15;
            cp16(Bs + (uint32_t)((r*B_LDH + g*8)*2),
                 Bg + (size_t)(k0 + r)*N + g*8);
        }
        cp_commit();
    };
    auto compute = [&](int p) {
        const __half* As = smh + p*STAGE_H;
        const __half* Bs = As + GBM*A_LDH;
        #pragma unroll
        for (int ks = 0; ks < 4; ks++) {
            wmma::fragment<wmma::matrix_a, 16, 16, 16, __half, wmma::row_major> af[4];
            wmma::fragment<wmma::matrix_b, 16, 16, 16, __half, wmma::row_major> bf[2];
            #pragma unroll
            for (int mi = 0; mi < 4; mi++)
                wmma::load_matrix_sync(af[mi], As + (wm + mi*16)*A_LDH + ks*16, A_LDH);
            #pragma unroll
            for (int ni = 0; ni < 2; ni++)
                wmma::load_matrix_sync(bf[ni], Bs + (ks*16)*B_LDH + wn + ni*16, B_LDH);
            #pragma unroll
            for (int mi = 0; mi < 4; mi++)
                #pragma unroll
                for (int ni = 0; ni < 2; ni++)
                    wmma::mma_sync(acc[mi][ni], af[mi], bf[ni], acc[mi][ni]);
        }
    };

    const int NC = K / GBK;
    issue_chunk(0);
    cp_wait<0>();
    __syncthreads();

    if (bias) {
        #pragma unroll
        for (int mi = 0; mi < 4; mi++)
            #pragma unroll
            for (int ni = 0; ni < 2; ni++)
                wmma::load_matrix_sync(acc[mi][ni], biasRep + wn + ni*16, GBN,
                                       wmma::mem_row_major);
    } else {
        #pragma unroll
        for (int mi = 0; mi < 4; mi++)
            #pragma unroll
            for (int ni = 0; ni < 2; ni++)
                wmma::fill_fragment(acc[mi][ni], 0.f);
    }

    for (int c = 0; c < NC; c++) {
        if (c > 0) {
            cp_wait<0>();
            __syncthreads();
        }
        if (c + 1 < NC) issue_chunk(c + 1);
        compute(c & 1);
    }

    if constexpr (std::is_same<TC, __half>::value) {
        #pragma unroll
        for (int mi = 0; mi < 4; mi++)
            #pragma unroll
            for (int ni = 0; ni < 2; ni++) {
                wmma::fragment<wmma::accumulator, 16, 16, 16, __half> h;
                #pragma unroll
                for (int t = 0; t < h.num_elements; t++)
                    h.x[t] = __float2half(acc[mi][ni].x[t]);
                wmma::store_matrix_sync(
                    C + (size_t)(by*GBM + wm + mi*16)*N + bx*GBN + wn + ni*16,
                    h, N, wmma::mem_row_major);
            }
    } else {
        #pragma unroll
        for (int mi = 0; mi < 4; mi++)
            #pragma unroll
            for (int ni = 0; ni < 2; ni++)
                wmma::store_matrix_sync(
                    C + (size_t)(by*GBM + wm + mi*16)*N + bx*GBN + wn + ni*16,
                    acc[mi][ni], N, wmma::mem_row_major);
    }
}

// ---------------------------------------------------------------------------
// RoPE on fused QKV buffer (which=0 -> Q cols, which=1 -> K cols)
// ---------------------------------------------------------------------------
__global__ void rope_kernel(__half* __restrict__ qkv)
{
    const int total = B * N_SEQ * HEADS * (ROT/2);
    int idx = blockIdx.x * blockDim.x + threadIdx.x;
    if (idx >= 2*total) return;
    const int which = (idx >= total);
    int t = idx - which*total;
    const int i   = t & 15;  t >>= 4;
    const int h   = t & 15;  t >>= 4;
    const int pos = t & (N_SEQ-1); t >>= 11;
    const int b   = t;

    const float inv_freq = powf(10000.f, -(float)(2*i) / (float)ROT);
    const float ang = (float)pos * inv_freq;
    float s, c;
    sincosf(ang, &s, &c);

    __half* base = qkv + ((size_t)(b*N_SEQ + pos)) * QKV_LD
                       + which*INNER + h*DH;
    const float x1 = __half2float(base[2*i]);
    const float x2 = __half2float(base[2*i+1]);
    base[2*i]   = __float2half(x1*c - x2*s);
    base[2*i+1] = __float2half(x2*c + x1*s);
}

// ---------------------------------------------------------------------------
// Flash attention: raw mma.sync, 32 q-rows/warp, AK=128 kv tiles, 2-stage
// cp.async. Software-pipelined exp: per chunk, order is S(jc) -> PV(jc-1) ->
// EX2(jc), so each MUFU burst has 32 independent HMMAs issued after it before
// its consumer. PV(7) drains before the stage barrier. Arithmetic identical
// to R16 (same values, same lsum order) -> rel_err must be bit-identical.
// ---------------------------------------------------------------------------
#define AQ   256
#define AK   128
#define ALD  72
#define OFF_QS 0
#define KV_SZ (AK*ALD)                  // 9216
#define OFF_K0 (AQ*ALD)                 // 18432
#define OFF_K1 (OFF_K0 + KV_SZ)
#define OFF_V0 (OFF_K1 + KV_SZ)
#define OFF_V1 (OFF_V0 + KV_SZ)
#define ATTN_H (OFF_V1 + KV_SZ)         // 55296 halfs
#define ATTN_SMEM (ATTN_H*2)            // 110592 B; x2 CTAs = 221184 < 228KB

__global__ __launch_bounds__(256, 2)
void attn_kernel(const __half* __restrict__ qkv, __half* __restrict__ out)
{
    extern __shared__ __half smh[];
    const uint32_t smbase = smem_u32(smh);

    const int bh = blockIdx.x;
    const int b  = bh >> 4;
    const int h  = bh & 15;
    const int qt = blockIdx.y;
    const int tid  = threadIdx.x;
    const int w    = tid >> 5;
    const int lane = tid & 31;
    const int gid  = lane >> 2;
    const int tig  = lane & 3;
    const int mi   = lane >> 3;

    // ---- load Q tile (256x64), scaled by SCALE*log2e
    const __half* qbase = qkv + ((size_t)(b*N_SEQ) + qt*AQ) * QKV_LD + h*DH;
    const __half2 sc2 = __floats2half2_rn(SCALE*LOG2E, SCALE*LOG2E);
    #pragma unroll
    for (int s = 0; s < 8; s++) {
        const int f = tid + s*256;
        const int r = f >> 3, g = f & 7;
        uint4 v = *(const uint4*)(qbase + (size_t)r*QKV_LD + g*8);
        __half2* hp = (__half2*)&v;
        #pragma unroll
        for (int j = 0; j < 4; j++) hp[j] = __hmul2(hp[j], sc2);
        *(uint4*)(smh + OFF_QS + r*ALD + g*8) = v;
    }

    const __half* kv_bh = qkv + ((size_t)(b*N_SEQ)) * QKV_LD + INNER + h*DH;
    auto issue_tile = [&](int kt) {
        const int p = kt & 1;
        const __half* kbase = kv_bh + (size_t)(kt*AK) * QKV_LD;
        const uint32_t Kb = smbase + (uint32_t)((p ? OFF_K1 : OFF_K0) * 2);
        const uint32_t Vb = smbase + (uint32_t)((p ? OFF_V1 : OFF_V0) * 2);
        #pragma unroll
        for (int s = 0; s < 4; s++) {
            const int f = tid + s*256;
            const int r = f >> 3, g = f & 7;
            const uint32_t off = (uint32_t)((r*ALD + g*8) * 2);
            cp16(Kb + off, kbase + (size_t)r*QKV_LD + g*8);
            cp16(Vb + off, kbase + INNER + (size_t)r*QKV_LD + g*8);
        }
        cp_commit();
    };

    issue_tile(0);
    __syncthreads();

    uint32_t qa[2][4][4];
    #pragma unroll
    for (int m = 0; m < 2; m++) {
        const int qrow = w*32 + m*16 + (mi & 1)*8 + (lane & 7);
        #pragma unroll
        for (int kk = 0; kk < 4; kk++) {
            const uint32_t a = smbase +
                (uint32_t)((OFF_QS + qrow*ALD + kk*16 + (mi >> 1)*8) * 2);
            ldsm_x4(qa[m][kk][0], qa[m][kk][1], qa[m][kk][2], qa[m][kk][3], a);
        }
    }

    float o[2][8][4];
    #pragma unroll
    for (int m = 0; m < 2; m++)
        #pragma unroll
        for (int nt = 0; nt < 8; nt++)
            #pragma unroll
            for (int e = 0; e < 4; e++) o[m][nt][e] = 0.f;
    float lsum[2][2];
    lsum[0][0] = lsum[0][1] = lsum[1][0] = lsum[1][1] = 0.f;

    const int krow_base = ((mi >> 1) << 3) + (lane & 7);
    const int kcol_off  = (mi & 1) * 8;
    const int vrow_base = ((mi & 1) << 3) + (lane & 7);
    const int vcol_off  = (mi >> 1) * 8;

    const int NT = N_SEQ/AK;   // 16
    for (int kt = 0; kt < NT; kt++) {
        const int p = kt & 1;
        cp_wait<0>();
        __syncthreads();
        if (kt + 1 < NT) issue_tile(kt + 1);

        const uint32_t Kb = smbase + (uint32_t)((p ? OFF_K1 : OFF_K0) * 2);
        const uint32_t Vb = smbase + (uint32_t)((p ? OFF_V1 : OFF_V0) * 2);

        uint32_t pa[2][4];   // pipelined P fragments (chunk jc-1)

        // PV for chunk jcp using current pa
        auto pv = [&](int jcp) {
            const int vrow = jcp*16 + vrow_base;
            #pragma unroll
            for (int vp = 0; vp < 4; vp++) {
                uint32_t v0, v1, v2, v3;
                ldsm_x4_t(v0, v1, v2, v3,
                          Vb + (uint32_t)((vrow*ALD + vp*16 + vcol_off) * 2));
                mma16816(o[0][2*vp],   pa[0], v0, v1);
                mma16816(o[0][2*vp+1], pa[0], v2, v3);
                mma16816(o[1][2*vp],   pa[1], v0, v1);
                mma16816(o[1][2*vp+1], pa[1], v2, v3);
            }
        };

        #pragma unroll
        for (int jc = 0; jc < 8; jc++) {
            // ---- S(jc)
            float sa0[4] = {0.f,0.f,0.f,0.f};
            float sa1[4] = {0.f,0.f,0.f,0.f};
            float sb0[4] = {0.f,0.f,0.f,0.f};
            float sb1[4] = {0.f,0.f,0.f,0.f};
            const int krow = jc*16 + krow_base;
            #pragma unroll
            for (int kk = 0; kk < 4; kk++) {
                uint32_t b0, b1, b2, b3;
                ldsm_x4(b0, b1, b2, b3,
                        Kb + (uint32_t)((krow*ALD + kk*16 + kcol_off) * 2));
                mma16816(sa0, qa[0][kk], b0, b1);
                mma16816(sa1, qa[0][kk], b2, b3);
                mma16816(sb0, qa[1][kk], b0, b1);
                mma16816(sb1, qa[1][kk], b2, b3);
            }
            // ---- PV(jc-1): independent HMMAs overlapping prior EX2 latency
            if (jc > 0) pv(jc - 1);
            // ---- EX2(jc) -> pa; lsum (same value order as R16)
            {
                const float e00 = ex2f(sa0[0]), e01 = ex2f(sa0[1]);
                const float e02 = ex2f(sa0[2]), e03 = ex2f(sa0[3]);
                const float e10 = ex2f(sa1[0]), e11 = ex2f(sa1[1]);
                const float e12 = ex2f(sa1[2]), e13 = ex2f(sa1[3]);
                pa[0][0] = f2h2(e00, e01);
                pa[0][1] = f2h2(e02, e03);
                pa[0][2] = f2h2(e10, e11);
                pa[0][3] = f2h2(e12, e13);
                lsum[0][0] += (e00 + e01) + (e10 + e11);
                lsum[0][1] += (e02 + e03) + (e12 + e13);
            }
            {
                const float e00 = ex2f(sb0[0]), e01 = ex2f(sb0[1]);
                const float e02 = ex2f(sb0[2]), e03 = ex2f(sb0[3]);
                const float e10 = ex2f(sb1[0]), e11 = ex2f(sb1[1]);
                const float e12 = ex2f(sb1[2]), e13 = ex2f(sb1[3]);
                pa[1][0] = f2h2(e00, e01);
                pa[1][1] = f2h2(e02, e03);
                pa[1][2] = f2h2(e10, e11);
                pa[1][3] = f2h2(e12, e13);
                lsum[1][0] += (e00 + e01) + (e10 + e11);
                lsum[1][1] += (e02 + e03) + (e12 + e13);
            }
        }
        pv(7);   // drain before the next barrier (V stage about to be refilled)
    }

    #pragma unroll
    for (int m = 0; m < 2; m++) {
        float l0 = lsum[m][0], l1 = lsum[m][1];
        l0 += __shfl_xor_sync(0xFFFFFFFFu, l0, 1);
        l0 += __shfl_xor_sync(0xFFFFFFFFu, l0, 2);
        l1 += __shfl_xor_sync(0xFFFFFFFFu, l1, 1);
        l1 += __shfl_xor_sync(0xFFFFFFFFu, l1, 2);
        const float inv0 = 1.f / l0;
        const float inv1 = 1.f / l1;

        const int r0 = qt*AQ + w*32 + m*16 + gid;
        __half* ob0 = out + ((size_t)(b*N_SEQ) + r0) * INNER + h*DH + tig*2;
        __half* ob1 = ob0 + (size_t)8 * INNER;
        #pragma unroll
        for (int nt = 0; nt < 8; nt++) {
            *(uint32_t*)(ob0 + nt*8) = f2h2(o[m][nt][0]*inv0, o[m][nt][1]*inv0);
            *(uint32_t*)(ob1 + nt*8) = f2h2(o[m][nt][2]*inv1, o[m][nt][3]*inv1);
        }
    }
}

// ---------------------------------------------------------------------------
// launch
// ---------------------------------------------------------------------------
extern "C" void kernel_launch(void* const* d_in, const int* in_sizes, int n_in,
                              void* d_out, int out_size)
{
    const float* queries = (const float*)d_in[0];
    const float* Wq      = (const float*)d_in[1];
    const float* Wkv     = (const float*)d_in[2];
    const float* Wout    = (const float*)d_in[3];
    const float* bout    = (const float*)d_in[4];
    float* out = (float*)d_out;

    __half *qkv, *attnp, *qh, *wqkv, *wo;
    cudaGetSymbolAddress((void**)&qkv,   g_qkv);
    cudaGetSymbolAddress((void**)&attnp, g_attn);
    cudaGetSymbolAddress((void**)&qh,    g_qh);
    cudaGetSymbolAddress((void**)&wqkv,  g_wqkv);
    cudaGetSymbolAddress((void**)&wo,    g_wo);

    static bool attr_set = false;
    if (!attr_set) {
        cudaFuncSetAttribute(attn_kernel,
                             cudaFuncAttributeMaxDynamicSharedMemorySize,
                             (int)ATTN_SMEM);
        cudaFuncSetAttribute(gemm_f16_kernel<__half>,
                             cudaFuncAttributeMaxDynamicSharedMemorySize,
                             GEMM_SMEM);
        cudaFuncSetAttribute(gemm_f16_kernel<float>,
                             cudaFuncAttributeMaxDynamicSharedMemorySize,
                             GEMM_SMEM);
        attr_set = true;
    }

    const int M = B * N_SEQ;  // 8192

    // ---- one-shot fp32 -> fp16 conversions (single merged launch)
    f2h_all_kernel<<<(N8_ALL + 255)/256, 256>>>(queries, Wq, Wkv, Wout,
                                                qh, wqkv, wo);

    // QKV = queries @ [Wq|Wkv]  -> half [8192, 3072]
    {
        dim3 grid(QKV_LD/GBN, M/GBM);   // 1536 CTAs
        gemm_f16_kernel<__half><<<grid, 256, GEMM_SMEM>>>(
            qh, wqkv, nullptr, qkv, M, QKV_LD, D_MODEL);
    }
    // RoPE (in-place on Q and K column blocks)
    {
        const int total = 2 * B * N_SEQ * HEADS * (ROT/2);
        rope_kernel<<<(total + 255)/256, 256>>>(qkv);
    }
    // attention -> half
    {
        dim3 grid(B*HEADS, N_SEQ/AQ);
        attn_kernel<<<grid, 256, ATTN_SMEM>>>(qkv, attnp);
    }
    // out = attn @ Wout + bout -> float
    {
        dim3 grid(D_MODEL/GBN, M/GBM);
        gemm_f16_kernel<float><<<grid, 256, GEMM_SMEM>>>(
            attnp, wo, bout, out, M, D_MODEL, INNER);
    }
}